// round 5
// baseline (speedup 1.0000x reference)
#include <cuda_runtime.h>

// B=2, C=8, 256x256 -> 1024x1024, CDF2.3 23-tap, two polyphase stages.
// Sparsity: odd taps all zero except w[11]; 12 even taps dense (values read
// from the real weight input each launch).
#define CH    8
#define NB    16
#define KTAPS 23

__device__ float g_s1[16ull * 512 * 512];   // stage-1 output (16MB)

// ---------------------------------------------------------------------------
// Fused upsample stage: in (NB,H,W) -> out (NB,2H,2W), phase O.
// Per block: output tile 32 rows x 256 cols.
//   Phase 1: load circular input tile s_in[27][144]  (rows t0.., cols c0-8..)
//   Phase 2: horizontal polyphase -> s_tmp[27][256]
//     O=1: tmp[2c]=Σ in[c-6+t]we[t], tmp[2c+1]=in[c]w11
//     O=0: tmp[2c]=in[c]w11,          tmp[2c+1]=Σ in[c-5+t]we[t]
//   Phase 3: vertical polyphase, 1 col/thread, 27-row register window
//     O=1 (t0=y0/2-6): j even: Σ r[j/2+t]we[t];   j odd: r[(j-1)/2+6]w11
//     O=0 (t0=y0/2-5): j even: r[j/2+5]w11;       j odd: Σ r[(j-1)/2+t]we[t]
// ---------------------------------------------------------------------------
template<int O, int H, int W>
__global__ void __launch_bounds__(256) fstage(const float* __restrict__ in,
                                              float* __restrict__ out,
                                              const float* __restrict__ wt)
{
    __shared__ float s_in[27][144];
    __shared__ float s_tmp[27][256];

    const int n = blockIdx.z;
    const float* wb = wt + (n & (CH - 1)) * KTAPS;
    float we[12];
#pragma unroll
    for (int t = 0; t < 12; t++) we[t] = __ldg(&wb[2 * t]);
    const float w11 = __ldg(&wb[11]);

    const int x0 = blockIdx.x * 256;        // output col base
    const int y0 = blockIdx.y * 32;         // output row base
    const int c0 = x0 >> 1;                 // input col base
    const int t0 = (y0 >> 1) - 5 - O;       // input row base (may be negative)
    const int tid = threadIdx.x;

    // Phase 1: circular load of 27 x 144 input tile.
    const float* __restrict__ ibase = in + (size_t)n * H * W;
    for (int idx = tid; idx < 27 * 144; idx += 256) {
        const int rr = idx / 144, ll = idx - rr * 144;
        const int gr = (t0 + rr + H) & (H - 1);
        const int gc = (c0 - 8 + ll + W) & (W - 1);
        s_in[rr][ll] = ibase[(size_t)gr * W + gc];
    }
    __syncthreads();

    // Phase 2: horizontal polyphase into s_tmp. local col lc -> input col c0+lc,
    // s_in local l corresponds to input col c0-8+l.
    for (int idx = tid; idx < 27 * 128; idx += 256) {
        const int rr = idx >> 7, lc = idx & 127;
        float cv = 0.f;
        if (O == 1) {
#pragma unroll
            for (int t = 0; t < 12; t++) cv = fmaf(s_in[rr][lc + 2 + t], we[t], cv);
            s_tmp[rr][2 * lc]     = cv;
            s_tmp[rr][2 * lc + 1] = s_in[rr][lc + 8] * w11;
        } else {
#pragma unroll
            for (int t = 0; t < 12; t++) cv = fmaf(s_in[rr][lc + 3 + t], we[t], cv);
            s_tmp[rr][2 * lc]     = s_in[rr][lc + 8] * w11;
            s_tmp[rr][2 * lc + 1] = cv;
        }
    }
    __syncthreads();

    // Phase 3: vertical polyphase; thread = one output column, 32 rows.
    const int x = tid;
    float r[27];
#pragma unroll
    for (int q = 0; q < 27; q++) r[q] = s_tmp[q][x];

    float* __restrict__ obase =
        out + ((size_t)n * 2 * H + y0) * (2 * W) + x0 + x;

#pragma unroll
    for (int j = 0; j < 32; j++) {
        float a;
        if (O == 1) {
            if ((j & 1) == 0) {
                a = 0.f;
#pragma unroll
                for (int t = 0; t < 12; t++) a = fmaf(r[(j >> 1) + t], we[t], a);
            } else {
                a = r[((j - 1) >> 1) + 6] * w11;
            }
        } else {
            if ((j & 1) == 0) {
                a = r[(j >> 1) + 5] * w11;
            } else {
                a = 0.f;
#pragma unroll
                for (int t = 0; t < 12; t++) a = fmaf(r[((j - 1) >> 1) + t], we[t], a);
            }
        }
        obase[(size_t)j * (2 * W)] = a;
    }
}

extern "C" void kernel_launch(void* const* d_in, const int* in_sizes, int n_in,
                              void* d_out, int out_size)
{
    (void)in_sizes; (void)n_in; (void)out_size;
    const float* img = (const float*)d_in[0];   // (2,8,256,256)
    const float* wt  = (const float*)d_in[1];   // (8,23)
    float* out = (float*)d_out;                 // (2,8,1024,1024)

    float* s1;
    cudaGetSymbolAddress((void**)&s1, g_s1);

    // Stage 1 (O=1): 256x256 -> 512x512. Tiles 32x256 -> grid (2,16,16).
    fstage<1, 256, 256><<<dim3(2, 16, NB), 256>>>(img, s1, wt);

    // Stage 2 (O=0): 512x512 -> 1024x1024. Tiles 32x256 -> grid (4,32,16).
    fstage<0, 512, 512><<<dim3(4, 32, NB), 256>>>(s1, out, wt);
}

// round 8
// speedup vs baseline: 1.1852x; 1.1852x over previous
#include <cuda_runtime.h>

// B=2, C=8, 256x256 -> 1024x1024, CDF2.3 23-tap, two polyphase stages.
// Sparsity: odd taps all zero except w[11]; 12 even taps dense (values read
// from the real weight input each launch).
#define CH    8
#define NB    16
#define KTAPS 23

__device__ float g_s1[16ull * 512 * 512];   // stage-1 output (16MB)

// ---------------------------------------------------------------------------
// Fused upsample stage: in (NB,H,W) -> out (NB,2H,2W), phase O.
// Output tile per block: 32 rows x 256 cols; 256 threads.
//  P1: load circular input tile s_in[27][144] (rows t0.., cols c0-8..)
//  P2: horizontal polyphase -> s_tmp[27][256], 4-col register groups:
//     O=1: tmp[2c]=conv(we), tmp[2c+1]=in[c]*w11
//     O=0: tmp[2c]=in[c]*w11, tmp[2c+1]=conv(we)
//  P3: vertical polyphase; thread = (col-pair p, row-half h), 19-row float2
//      window from s_tmp[8h + q][2p], 16 float2 stores.
// ---------------------------------------------------------------------------
template<int O, int H, int W>
__global__ void __launch_bounds__(256) fstage(const float* __restrict__ in,
                                              float* __restrict__ out,
                                              const float* __restrict__ wt)
{
    __shared__ float s_in[27][144];
    __shared__ float s_tmp[27][256];

    const int n = blockIdx.z;
    const float* wb = wt + (n & (CH - 1)) * KTAPS;
    float we[12];
#pragma unroll
    for (int t = 0; t < 12; t++) we[t] = __ldg(&wb[2 * t]);
    const float w11 = __ldg(&wb[11]);

    const int x0 = blockIdx.x * 256;        // output col base
    const int y0 = blockIdx.y * 32;         // output row base
    const int c0 = x0 >> 1;                 // input col base
    const int t0 = (y0 >> 1) - 5 - O;       // input row base (may be negative)
    const int tid = threadIdx.x;

    // ---- Phase 1: load 27 x 144 circular input tile ----
    const float* __restrict__ ibase = in + (size_t)n * H * W;
    if (c0 >= 8 && c0 + 136 <= W) {
        // columns interior: vectorized rows (rows still circular via mask)
        for (int idx = tid; idx < 27 * 36; idx += 256) {
            const int rr = idx / 36, cc = idx - rr * 36;
            const int gr = (t0 + rr + H) & (H - 1);
            *(float4*)&s_in[rr][4 * cc] =
                *(const float4*)(ibase + (size_t)gr * W + (c0 - 8) + 4 * cc);
        }
    } else {
        for (int idx = tid; idx < 27 * 144; idx += 256) {
            const int rr = idx / 144, ll = idx - rr * 144;
            const int gr = (t0 + rr + H) & (H - 1);
            const int gc = (c0 - 8 + ll + W) & (W - 1);
            s_in[rr][ll] = ibase[(size_t)gr * W + gc];
        }
    }
    __syncthreads();

    // ---- Phase 2: horizontal polyphase, 4 cols/group ----
    // group g: rr = g>>5, lc0 = (g&31)*4; window v[0..19] = s_in[rr][lc0..lc0+19]
    for (int g = tid; g < 27 * 32; g += 256) {
        const int rr = g >> 5, lc0 = (g & 31) << 2;
        float v[20];
#pragma unroll
        for (int q = 0; q < 5; q++) {
            float4 f = *(const float4*)&s_in[rr][lc0 + 4 * q];
            v[4 * q] = f.x; v[4 * q + 1] = f.y; v[4 * q + 2] = f.z; v[4 * q + 3] = f.w;
        }
        float o8[8];
#pragma unroll
        for (int i = 0; i < 4; i++) {
            float cv = 0.f;
            if (O == 1) {
#pragma unroll
                for (int t = 0; t < 12; t++) cv = fmaf(v[i + 2 + t], we[t], cv);
                o8[2 * i]     = cv;
                o8[2 * i + 1] = v[i + 8] * w11;
            } else {
#pragma unroll
                for (int t = 0; t < 12; t++) cv = fmaf(v[i + 3 + t], we[t], cv);
                o8[2 * i]     = v[i + 8] * w11;
                o8[2 * i + 1] = cv;
            }
        }
        *(float4*)&s_tmp[rr][2 * lc0]     = make_float4(o8[0], o8[1], o8[2], o8[3]);
        *(float4*)&s_tmp[rr][2 * lc0 + 4] = make_float4(o8[4], o8[5], o8[6], o8[7]);
    }
    __syncthreads();

    // ---- Phase 3: vertical polyphase; (p, h) = (col-pair, row-half) ----
    const int p = tid & 127;     // column pair: cols 2p, 2p+1
    const int h = tid >> 7;      // row half: rows j = 16h .. 16h+15
    const int qb = 8 * h;

    float2 r[19];
#pragma unroll
    for (int q = 0; q < 19; q++)
        r[q] = *(const float2*)&s_tmp[qb + q][2 * p];

    float* __restrict__ obase =
        out + ((size_t)n * 2 * H + y0 + 16 * h) * (2 * W) + x0 + 2 * p;

#pragma unroll
    for (int j = 0; j < 16; j++) {      // local row within half
        float2 a;
        if (O == 1) {
            if ((j & 1) == 0) {         // conv row
                a = make_float2(0.f, 0.f);
                const int q0 = j >> 1;
#pragma unroll
                for (int t = 0; t < 12; t++) {
                    const float2 v = r[q0 + t];
                    a.x = fmaf(v.x, we[t], a.x);
                    a.y = fmaf(v.y, we[t], a.y);
                }
            } else {                    // copy row
                const float2 v = r[((j - 1) >> 1) + 6];
                a = make_float2(v.x * w11, v.y * w11);
            }
        } else {
            if ((j & 1) == 0) {         // copy row
                const float2 v = r[(j >> 1) + 5];
                a = make_float2(v.x * w11, v.y * w11);
            } else {                    // conv row
                a = make_float2(0.f, 0.f);
                const int q0 = (j - 1) >> 1;
#pragma unroll
                for (int t = 0; t < 12; t++) {
                    const float2 v = r[q0 + t];
                    a.x = fmaf(v.x, we[t], a.x);
                    a.y = fmaf(v.y, we[t], a.y);
                }
            }
        }
        *(float2*)(obase + (size_t)j * (2 * W)) = a;
    }
}

extern "C" void kernel_launch(void* const* d_in, const int* in_sizes, int n_in,
                              void* d_out, int out_size)
{
    (void)in_sizes; (void)n_in; (void)out_size;
    const float* img = (const float*)d_in[0];   // (2,8,256,256)
    const float* wt  = (const float*)d_in[1];   // (8,23)
    float* out = (float*)d_out;                 // (2,8,1024,1024)

    float* s1;
    cudaGetSymbolAddress((void**)&s1, g_s1);

    // Stage 1 (O=1): 256x256 -> 512x512. grid (2,16,16).
    fstage<1, 256, 256><<<dim3(2, 16, NB), 256>>>(img, s1, wt);

    // Stage 2 (O=0): 512x512 -> 1024x1024. grid (4,32,16).
    fstage<0, 512, 512><<<dim3(4, 32, NB), 256>>>(s1, out, wt);
}

// round 9
// speedup vs baseline: 1.4375x; 1.2129x over previous
#include <cuda_runtime.h>

// B=2, C=8, 256x256 -> 1024x1024, CDF2.3 23-tap, two polyphase stages.
// Sparsity: odd taps all zero except w[11]; 12 even taps dense (values read
// from the real weight input each launch).
#define CH    8
#define NB    16
#define KTAPS 23

__device__ float g_s1[16ull * 512 * 512];   // stage-1 output (16MB)

// ---------------------------------------------------------------------------
// Fused upsample stage: in (NB,H,W) -> out (NB,2H,2W), phase O.
// Output tile per block: 32 rows x 256 cols; 256 threads; smem = s_tmp only.
//  Phase H: horizontal polyphase DIRECT from global (20-float window per
//    4-col job, per-job interior check) -> s_tmp[27][256].
//     O=1: tmp[2c]=conv(we) over v[i+2..], tmp[2c+1]=v[i+8]*w11
//     O=0: tmp[2c]=v[i+8]*w11, tmp[2c+1]=conv(we) over v[i+3..]
//  Phase V: vertical polyphase; thread = (col-pair p, row-half h).
//    Rolling 12-row float2 window win[q]=r[i+q]; per step i emits
//    conv row = sum win[t]*we[t] and copy row = win[5+O]*w11.
//     O=0: row 2i = copy, row 2i+1 = conv.  O=1: row 2i = conv, 2i+1 = copy.
// ---------------------------------------------------------------------------
template<int O, int H, int W>
__global__ void __launch_bounds__(256) fstage(const float* __restrict__ in,
                                              float* __restrict__ out,
                                              const float* __restrict__ wt)
{
    __shared__ float s_tmp[27][256];

    const int n = blockIdx.z;
    const float* wb = wt + (n & (CH - 1)) * KTAPS;
    float we[12];
#pragma unroll
    for (int t = 0; t < 12; t++) we[t] = __ldg(&wb[2 * t]);
    const float w11 = __ldg(&wb[11]);

    const int x0 = blockIdx.x * 256;        // output col base
    const int y0 = blockIdx.y * 32;         // output row base
    const int c0 = x0 >> 1;                 // input col base
    const int t0 = (y0 >> 1) - 5 - O;       // input row base (may be negative)
    const int tid = threadIdx.x;

    const float* __restrict__ ibase = in + (size_t)n * H * W;

    // ---- Phase H: 27 rows x 32 four-col jobs, direct from global ----
    for (int g = tid; g < 27 * 32; g += 256) {
        const int rr = g >> 5, lc0 = (g & 31) << 2;
        const int gr = (t0 + rr + H) & (H - 1);
        const float* __restrict__ row = ibase + (size_t)gr * W;
        const int cb = c0 - 8 + lc0;        // window = input cols [cb, cb+19]

        float v[20];
        if (cb >= 0 && cb + 20 <= W) {      // aligned: cb % 4 == 0 by construction
#pragma unroll
            for (int q = 0; q < 5; q++) {
                float4 f = *(const float4*)(row + cb + 4 * q);
                v[4 * q] = f.x; v[4 * q + 1] = f.y;
                v[4 * q + 2] = f.z; v[4 * q + 3] = f.w;
            }
        } else {
#pragma unroll
            for (int q = 0; q < 20; q++)
                v[q] = row[(cb + q + W) & (W - 1)];
        }

        float o8[8];
#pragma unroll
        for (int i = 0; i < 4; i++) {
            float cv = 0.f;
            if (O == 1) {
#pragma unroll
                for (int t = 0; t < 12; t++) cv = fmaf(v[i + 2 + t], we[t], cv);
                o8[2 * i]     = cv;
                o8[2 * i + 1] = v[i + 8] * w11;
            } else {
#pragma unroll
                for (int t = 0; t < 12; t++) cv = fmaf(v[i + 3 + t], we[t], cv);
                o8[2 * i]     = v[i + 8] * w11;
                o8[2 * i + 1] = cv;
            }
        }
        *(float4*)&s_tmp[rr][2 * lc0]     = make_float4(o8[0], o8[1], o8[2], o8[3]);
        *(float4*)&s_tmp[rr][2 * lc0 + 4] = make_float4(o8[4], o8[5], o8[6], o8[7]);
    }
    __syncthreads();

    // ---- Phase V: rolling-window vertical polyphase ----
    const int p = tid & 127;     // column pair: cols 2p, 2p+1
    const int h = tid >> 7;      // row half: output rows 16h .. 16h+15
    const int qb = 8 * h;        // s_tmp row base for this half

    float* __restrict__ obase =
        out + ((size_t)n * 2 * H + y0 + 16 * h) * (2 * W) + x0 + 2 * p;

    float2 win[12];
#pragma unroll
    for (int q = 0; q < 12; q++)
        win[q] = *(const float2*)&s_tmp[qb + q][2 * p];

#pragma unroll
    for (int i = 0; i < 8; i++) {
        const float2 cp = win[5 + O];
        float2 cv = make_float2(0.f, 0.f);
#pragma unroll
        for (int t = 0; t < 12; t++) {
            cv.x = fmaf(win[t].x, we[t], cv.x);
            cv.y = fmaf(win[t].y, we[t], cv.y);
        }
        const float2 cpv = make_float2(cp.x * w11, cp.y * w11);
        if (O == 0) {
            *(float2*)(obase + (size_t)(2 * i)     * (2 * W)) = cpv;
            *(float2*)(obase + (size_t)(2 * i + 1) * (2 * W)) = cv;
        } else {
            *(float2*)(obase + (size_t)(2 * i)     * (2 * W)) = cv;
            *(float2*)(obase + (size_t)(2 * i + 1) * (2 * W)) = cpv;
        }
        if (i < 7) {
#pragma unroll
            for (int q = 0; q < 11; q++) win[q] = win[q + 1];
            win[11] = *(const float2*)&s_tmp[qb + i + 12][2 * p];
        }
    }
}

extern "C" void kernel_launch(void* const* d_in, const int* in_sizes, int n_in,
                              void* d_out, int out_size)
{
    (void)in_sizes; (void)n_in; (void)out_size;
    const float* img = (const float*)d_in[0];   // (2,8,256,256)
    const float* wt  = (const float*)d_in[1];   // (8,23)
    float* out = (float*)d_out;                 // (2,8,1024,1024)

    float* s1;
    cudaGetSymbolAddress((void**)&s1, g_s1);

    // Stage 1 (O=1): 256x256 -> 512x512. grid (2,16,16).
    fstage<1, 256, 256><<<dim3(2, 16, NB), 256>>>(img, s1, wt);

    // Stage 2 (O=0): 512x512 -> 1024x1024. grid (4,32,16).
    fstage<0, 512, 512><<<dim3(4, 32, NB), 256>>>(s1, out, wt);
}